// round 17
// baseline (speedup 1.0000x reference)
#include <cuda_runtime.h>
#include <cuda_fp16.h>
#include <cstdint>

// ---------------- problem constants ----------------
#define Hc    128
#define H1c   129
#define NROW  (H1c*H1c)         // 16641 (i,j) rows, each 129 k long
#define Bq    64
#define N1    64
#define N2    32
#define NCTA  304               // 2 CTAs per SM
#define NTHR  256               // 8 warps
#define RPC   55                // rows per CTA (304*55 = 16720 >= 16641)

#define ST_STRIDE 132           // sT row stride (f32, staged)
#define PH        72            // sH pitch in halves (64 + 8 pad)
#define STG_F     (H1c*N1)      // 8256 floats per stage slot (33024 B)
#define SH_H      (Hc*PH)       // 9216 halves (single sH buf, 18432 B)

// smem layout (float offsets)                     bytes
#define SM_PM     0             // sPM: 55 x 64     14080
#define SM_STAGE  3520          // stage: 2 x 8256  66048
#define SM_H      20032         // sH: 4608 f       18432
#define SM_R      24640         // sR: 64 f (W1 row 128 of current r)
#define SM_MBAR   24704         // 2 mbarriers
#define SM_FLOATS 24708         // 98832 B/CTA (x2 = 197664 <= 227KB)

#define R_BYTES   (H1c * N1 * 4)    // 33024

__device__ float    g_Y1pre[Bq * N1];   // REDG accumulator; zero-init, self-cleaning
__device__ unsigned g_ctr;              // last-CTA counter; zero-init, self-cleaning

// ---------------- helpers ----------------
__device__ __forceinline__ uint32_t smem_u32(const void* p) {
    uint32_t a;
    asm("{ .reg .u64 t; cvta.to.shared.u64 t, %1; cvt.u32.u64 %0, t; }" : "=r"(a) : "l"(p));
    return a;
}
__device__ __forceinline__ uint32_t packh2(float lo, float hi) {
    __half2 h = __floats2half2_rn(lo, hi);
    return *reinterpret_cast<uint32_t*>(&h);
}
__device__ __forceinline__ void mbar_init(uint32_t a, uint32_t cnt) {
    asm volatile("mbarrier.init.shared.b64 [%0], %1;" :: "r"(a), "r"(cnt) : "memory");
}
__device__ __forceinline__ void mbar_expect_tx(uint32_t a, uint32_t bytes) {
    asm volatile("mbarrier.arrive.expect_tx.shared.b64 _, [%0], %1;"
                 :: "r"(a), "r"(bytes) : "memory");
}
__device__ __forceinline__ void bulk_g2s(uint32_t dst, const void* src,
                                         uint32_t bytes, uint32_t mbar) {
    asm volatile(
        "cp.async.bulk.shared::cluster.global.mbarrier::complete_tx::bytes "
        "[%0], [%1], %2, [%3];"
        :: "r"(dst), "l"(src), "r"(bytes), "r"(mbar) : "memory");
}
__device__ __forceinline__ void mbar_wait(uint32_t a, uint32_t par) {
    uint32_t done;
    asm volatile("{\n\t.reg .pred p;\n\t"
                 "mbarrier.try_wait.parity.acquire.cta.shared::cta.b64 p, [%1], %2;\n\t"
                 "selp.b32 %0,1,0,p;\n\t}" : "=r"(done) : "r"(a), "r"(par) : "memory");
    if (!done) {
        asm volatile("{\n\t.reg .pred P1;\n\tW%=:\n\t"
                     "mbarrier.try_wait.parity.acquire.cta.shared::cta.b64 P1, [%0], %1, 0x989680;\n\t"
                     "@P1 bra.uni D%=;\n\tbra.uni W%=;\n\tD%=:\n\t}"
                     :: "r"(a), "r"(par) : "memory");
    }
}
// ldmatrix x4 transposed b16: 16x16 tile -> B frags for two n8 columns
__device__ __forceinline__ void ldm_x4_trans(uint32_t& q0, uint32_t& q1,
                                             uint32_t& q2, uint32_t& q3,
                                             uint32_t addr) {
    asm volatile("ldmatrix.sync.aligned.m8n8.x4.trans.shared.b16 {%0,%1,%2,%3}, [%4];"
                 : "=r"(q0), "=r"(q1), "=r"(q2), "=r"(q3) : "r"(addr));
}
__device__ __forceinline__ void mma_f16(float* d, const uint32_t* a,
                                        uint32_t b0, uint32_t b1) {
    asm volatile(
        "mma.sync.aligned.m16n8k16.row.col.f32.f16.f16.f32 "
        "{%0,%1,%2,%3}, {%4,%5,%6,%7}, {%8,%9}, {%0,%1,%2,%3};"
        : "+f"(d[0]), "+f"(d[1]), "+f"(d[2]), "+f"(d[3])
        : "r"(a[0]), "r"(a[1]), "r"(a[2]), "r"(a[3]), "r"(b0), "r"(b1));
}

// ============================================================
// Kernel: factored GEMM, 2 CTAs/SM.
// Loop per r: MMA(r) uses ONLY sH/sR; the stage slot is consumed
// (and refilled) at repack time -> each 33KB bulk copy gets ~2
// iterations of lead over its consumer.
// ============================================================
__global__ void __launch_bounds__(NTHR, 2)
k_main(const float* __restrict__ v, const float* __restrict__ a,
       const float* __restrict__ t, const float* __restrict__ W1,
       const float* __restrict__ b1, const float* __restrict__ W2,
       const float* __restrict__ b2, const float* __restrict__ W3,
       const float* __restrict__ b3, float* __restrict__ out)
{
    extern __shared__ float sm[];
    float* sPM = sm + SM_PM;
    float* sR  = sm + SM_R;
    const uint32_t base  = smem_u32(sm);
    const uint32_t stg_u = base + SM_STAGE * 4;
    const uint32_t sh_u  = base + SM_H * 4;
    const uint32_t mb[2] = { base + SM_MBAR * 4, base + SM_MBAR * 4 + 8 };

    const int tid  = threadIdx.x;
    const int wid  = tid >> 5;
    const int lane = tid & 31;
    const int cta  = blockIdx.x;

    const int r0    = cta * RPC;
    const int nrows = (r0 < NROW) ? min(RPC, NROW - r0) : 0;

    if (nrows > 0) {
        const int i0 = r0 / H1c;
        const int i1 = (r0 + nrows - 1) / H1c;

        // ---- startup staging in the stage region (dead before first bulk) ----
        float* vT = sm + SM_STAGE;               // [c*65 + b]
        float* a2 = sm + SM_STAGE + 8320;        // [sel*64 + b]
        for (int idx = tid; idx < Bq * Hc; idx += NTHR) {
            int b = idx >> 7, c = idx & 127;
            vT[c * 65 + b] = v[idx];
        }
        if (tid < 128) {
            int c = tid >> 6, b = tid & 63;
            int ii = c ? i1 : i0;
            a2[c * 64 + b] = (ii == 0) ? 1.f : __ldg(&a[b * Hc + ii - 1]);
        }
        __syncthreads();

        for (int idx = tid; idx < nrows * Bq; idx += NTHR) {
            int rloc = idx >> 6, b = idx & 63;
            int rg = r0 + rloc;
            int i  = rg / H1c;
            int j  = rg - i * H1c;
            float av = (i == i0) ? a2[b] : a2[64 + b];
            float vv = (j == 0) ? 1.f : vT[(j - 1) * 65 + b];
            sPM[idx] = av * vv;
        }
        __syncthreads();                          // vT/a2 dead

        float* sT = sm + SM_STAGE;                // overwrite staging with T_h
        for (int idx = tid; idx < Bq * H1c; idx += NTHR) {
            int b = idx / H1c;
            int c = idx - b * H1c;
            sT[b * ST_STRIDE + c] = (c == 0) ? 1.f : __ldg(&t[b * Hc + c - 1]);
        }
        if (tid == 0) { mbar_init(mb[0], 1); mbar_init(mb[1], 1); }
        __syncthreads();

        // ---- warp geometry: 8 warps = 2(m32) x 4(n16) ----
        const int wm = wid & 1;
        const int wn = wid >> 1;                  // 0..3
        const int g  = lane >> 2;
        const int tk = lane & 3;

        // loop-invariant A fragments (T_h) in registers
        uint32_t afr[8][2][4];
        float ar[2][2];
        #pragma unroll
        for (int mi = 0; mi < 2; mi++) {
            const int mrow = wm * 32 + mi * 16 + g;
            const float* rA  = sT + mrow * ST_STRIDE;
            const float* rA8 = sT + (mrow + 8) * ST_STRIDE;
            #pragma unroll
            for (int ks = 0; ks < 8; ks++) {
                const int c = ks * 16 + 2 * tk;
                afr[ks][mi][0] = packh2(rA [c],     rA [c + 1]);
                afr[ks][mi][1] = packh2(rA8[c],     rA8[c + 1]);
                afr[ks][mi][2] = packh2(rA [c + 8], rA [c + 9]);
                afr[ks][mi][3] = packh2(rA8[c + 8], rA8[c + 9]);
            }
            ar[mi][0] = rA [128];
            ar[mi][1] = rA8[128];
        }
        __syncthreads();                          // sT dead -> stage usable

        // ---- prologue: bulks for r0 (slot 0) and r0+1 (slot 1) ----
        if (tid == 0) {
            mbar_expect_tx(mb[0], R_BYTES);
            bulk_g2s(stg_u, W1 + (long long)r0 * STG_F, R_BYTES, mb[0]);
            if (nrows > 1) {
                mbar_expect_tx(mb[1], R_BYTES);
                bulk_g2s(stg_u + STG_F * 4, W1 + (long long)(r0 + 1) * STG_F,
                         R_BYTES, mb[1]);
            }
        }

        // ldmatrix x4 lane address inside sH
        const int lrow = lane & 7;
        const int sel  = lane >> 3;
        const uint32_t lm_off =
            (uint32_t)((((sel & 1) * 8 + lrow) * PH + wn * 16 + (sel >> 1) * 8) * 2);

        // repack: stage slot sl -> sH (rows 0..127, f16) + sR (row 128, f32)
        auto repack = [&](int sl) {
            const float* st = sm + SM_STAGE + sl * STG_F;
            __half* dh = reinterpret_cast<__half*>(sm + SM_H);
            #pragma unroll
            for (int p = 0; p < 8; p++) {
                int idx = p * NTHR + tid;          // 0..2047
                int kk = idx >> 4, seg = idx & 15;
                float4 w = *reinterpret_cast<const float4*>(st + kk * 64 + seg * 4);
                uint2 u;
                u.x = packh2(w.x, w.y);
                u.y = packh2(w.z, w.w);
                *reinterpret_cast<uint2*>(dh + kk * PH + seg * 4) = u;
            }
            if (tid < 16)                          // row 128 -> sR (f32)
                *reinterpret_cast<float4*>(sR + tid * 4) =
                    *reinterpret_cast<const float4*>(st + 128 * 64 + tid * 4);
        };

        int ph[2] = {0, 0};
        mbar_wait(mb[0], ph[0]); ph[0] ^= 1;       // slot0 full
        repack(0);
        __syncthreads();                           // sH/sR(r=0) ready; slot0 dead
        if (tid == 0 && nrows > 2) {               // refill slot0 with r0+2
            mbar_expect_tx(mb[0], R_BYTES);
            bulk_g2s(stg_u, W1 + (long long)(r0 + 2) * STG_F, R_BYTES, mb[0]);
        }

        float dacc[2][2][4];
        #pragma unroll
        for (int mi = 0; mi < 2; mi++)
            #pragma unroll
            for (int nj = 0; nj < 2; nj++)
                #pragma unroll
                for (int q = 0; q < 4; q++) dacc[mi][nj][q] = 0.f;

        for (int r = 0; r < nrows; r++) {
            const int sl = r & 1;

            // ---- MMA(r): sH + sR only (no stage access) ----
            float gacc[2][2][4];
            #pragma unroll
            for (int mi = 0; mi < 2; mi++)
                #pragma unroll
                for (int nj = 0; nj < 2; nj++)
                    #pragma unroll
                    for (int q = 0; q < 4; q++) gacc[mi][nj][q] = 0.f;

            #pragma unroll
            for (int ks = 0; ks < 8; ks++) {
                uint32_t q0, q1, q2, q3;
                ldm_x4_trans(q0, q1, q2, q3, sh_u + lm_off + ks * (16 * PH * 2));
                mma_f16(gacc[0][0], afr[ks][0], q0, q1);
                mma_f16(gacc[1][0], afr[ks][1], q0, q1);
                mma_f16(gacc[0][1], afr[ks][0], q2, q3);
                mma_f16(gacc[1][1], afr[ks][1], q2, q3);
            }
            {   // fp32 rank-1 for k = 128 (from sR)
                #pragma unroll
                for (int nj = 0; nj < 2; nj++) {
                    float2 w0 = *reinterpret_cast<const float2*>(
                        sR + wn * 16 + nj * 8 + 2 * tk);
                    #pragma unroll
                    for (int mi = 0; mi < 2; mi++) {
                        gacc[mi][nj][0] += ar[mi][0] * w0.x;
                        gacc[mi][nj][1] += ar[mi][0] * w0.y;
                        gacc[mi][nj][2] += ar[mi][1] * w0.x;
                        gacc[mi][nj][3] += ar[mi][1] * w0.y;
                    }
                }
            }
            {   // epilogue: D += pm[r,row] * G
                const float* pmr = sPM + r * Bq;
                #pragma unroll
                for (int mi = 0; mi < 2; mi++) {
                    const int mrow = wm * 32 + mi * 16 + g;
                    float p0 = pmr[mrow];
                    float p1 = pmr[mrow + 8];
                    #pragma unroll
                    for (int nj = 0; nj < 2; nj++) {
                        dacc[mi][nj][0] += p0 * gacc[mi][nj][0];
                        dacc[mi][nj][1] += p0 * gacc[mi][nj][1];
                        dacc[mi][nj][2] += p1 * gacc[mi][nj][2];
                        dacc[mi][nj][3] += p1 * gacc[mi][nj][3];
                    }
                }
            }

            __syncthreads();                      // all warps done with sH/sR
            if (r + 1 < nrows) {                  // prepare sH/sR for r+1
                mbar_wait(mb[sl ^ 1], ph[sl ^ 1]); ph[sl ^ 1] ^= 1;
                repack(sl ^ 1);
                __syncthreads();                  // sH ready; slot sl^1 dead
                if (tid == 0 && r + 3 < nrows) {  // refill slot sl^1 with r+3
                    mbar_expect_tx(mb[sl ^ 1], R_BYTES);
                    bulk_g2s(stg_u + (sl ^ 1) * (STG_F * 4),
                             W1 + (long long)(r0 + r + 3) * STG_F, R_BYTES,
                             mb[sl ^ 1]);
                }
            }
        }

        // ---- accumulate into global Y1pre via REDG ----
        #pragma unroll
        for (int mi = 0; mi < 2; mi++) {
            const int mrow = wm * 32 + mi * 16 + g;
            #pragma unroll
            for (int nj = 0; nj < 2; nj++) {
                const int n = wn * 16 + nj * 8 + 2 * tk;
                atomicAdd(&g_Y1pre[mrow * N1 + n],           dacc[mi][nj][0]);
                atomicAdd(&g_Y1pre[mrow * N1 + n + 1],       dacc[mi][nj][1]);
                atomicAdd(&g_Y1pre[(mrow + 8) * N1 + n],     dacc[mi][nj][2]);
                atomicAdd(&g_Y1pre[(mrow + 8) * N1 + n + 1], dacc[mi][nj][3]);
            }
        }
    }

    // ---- last-CTA fused reduce + tail MLP ----
    __threadfence();
    __shared__ unsigned s_last;
    if (tid == 0) s_last = (atomicAdd(&g_ctr, 1u) == (unsigned)(gridDim.x - 1));
    __syncthreads();
    if (!s_last) return;

    float* sY1 = sm;                 // [b*65 + o], 4160 floats
    float* sW2 = sm + 4160;          // 2048
    float* sW3 = sm + 6208;          // 32
    float* sB2 = sm + 6240;          // 32

    for (int i = tid; i < N1 * N2; i += NTHR) sW2[i] = __ldg(&W2[i]);
    if (tid < N2) { sW3[tid] = __ldg(&W3[tid]); sB2[tid] = __ldg(&b2[tid]); }
    for (int i = tid; i < Bq * N1; i += NTHR) {
        int b = i >> 6, o = i & 63;
        float s;
        asm volatile("ld.global.cg.f32 %0, [%1];" : "=f"(s) : "l"(g_Y1pre + i));
        sY1[b * 65 + o] = fmaxf(s + __ldg(&b1[o]), 0.f);
    }
    __syncthreads();

    {   // 4 threads per batch row; each computes 8 layer-2 units
        const int b = tid >> 2;          // 0..63
        const int q = tid & 3;           // j-quarter
        float s8[8];
        #pragma unroll
        for (int jj = 0; jj < 8; jj++) s8[jj] = sB2[q * 8 + jj];
        #pragma unroll 8
        for (int o = 0; o < N1; o++) {
            float y = sY1[b * 65 + o];
            #pragma unroll
            for (int jj = 0; jj < 8; jj++)
                s8[jj] += y * sW2[o * N2 + q * 8 + jj];
        }
        float rq = 0.f;
        #pragma unroll
        for (int jj = 0; jj < 8; jj++)
            rq += fmaxf(s8[jj], 0.f) * sW3[q * 8 + jj];
        #pragma unroll
        for (int off = 2; off; off >>= 1)
            rq += __shfl_down_sync(0xFFFFFFFFu, rq, off, 4);
        if (q == 0) out[b] = rq + __ldg(&b3[0]);
    }
    __syncthreads();

    // self-clean for graph replay
    for (int i = tid; i < Bq * N1; i += NTHR) g_Y1pre[i] = 0.f;
    if (tid == 0) g_ctr = 0u;
}

// ============================================================
// Launch: v, a, t, W1, b1, W2, b2, W3, b3 ; out float[64]
// ============================================================
extern "C" void kernel_launch(void* const* d_in, const int* in_sizes, int n_in,
                              void* d_out, int out_size)
{
    const float *v  = (const float*)d_in[0];
    const float *a  = (const float*)d_in[1];
    const float *t  = (const float*)d_in[2];
    const float *W1 = (const float*)d_in[3];
    const float *b1 = (const float*)d_in[4];
    const float *W2 = (const float*)d_in[5];
    const float *b2 = (const float*)d_in[6];
    const float *W3 = (const float*)d_in[7];
    const float *b3 = (const float*)d_in[8];
    float *out = (float*)d_out;

    cudaFuncSetAttribute(k_main, cudaFuncAttributeMaxDynamicSharedMemorySize,
                         SM_FLOATS * 4);

    k_main<<<NCTA, NTHR, SM_FLOATS * 4>>>(v, a, t, W1, b1, W2, b2, W3, b3, out);
}